// round 10
// baseline (speedup 1.0000x reference)
#include <cuda_runtime.h>
#include <cstdint>
#include <math.h>

#define IN_DIM   256
#define OUT_DIM  256
#define GRIDN    12      // NUM + 1 + 2K
#define NB       8       // NUM + K
#define BATCH    2048
#define BT       4       // batches per block (1 per thread-group)
#define THREADS  256
#define OT       4       // outputs per shared tile
#define NT       (OUT_DIM / OT)

// Fused mask*scale, transposed to [o][i]
__device__ float g_sbT[OUT_DIM * IN_DIM];
__device__ float g_ssT[OUT_DIM * IN_DIM];

__global__ void init_kernel(const float* __restrict__ sb,
                            const float* __restrict__ ssp,
                            const float* __restrict__ mask,
                            float* __restrict__ ysum) {
    int idx = blockIdx.x * blockDim.x + threadIdx.x;
    if (idx < BATCH * OUT_DIM) ysum[idx] = 0.f;
    if (idx < IN_DIM * OUT_DIM) {
        int i = idx >> 8;
        int o = idx & 255;
        float m = mask[idx];
        g_sbT[o * IN_DIM + i] = m * sb[idx];
        g_ssT[o * IN_DIM + i] = m * ssp[idx];
    }
}

__device__ __forceinline__ void cp_async16(unsigned int saddr, const void* gaddr) {
    asm volatile("cp.async.cg.shared.global [%0], [%1], 16;\n"
                 :: "r"(saddr), "l"(gaddr));
}
__device__ __forceinline__ void cp_async_wait_all() {
    asm volatile("cp.async.commit_group;\ncp.async.wait_group 0;\n" ::: "memory");
}

__global__ __launch_bounds__(THREADS, 3)
void kan_kernel(const float* __restrict__ x,
                const float* __restrict__ grid,
                const float* __restrict__ coef,
                float* __restrict__ out) {
    // coef slab: [i][chunk] rows of 32 floats, XOR swizzle chunk ^ ((i>>2)&7)
    __shared__ float s_coef[IN_DIM * OT * NB];   // 32 KB
    __shared__ float s_sb[OT * IN_DIM];          // 4 KB
    __shared__ float s_ss[OT * IN_DIM];          // 4 KB

    const int tid  = threadIdx.x;
    const int quad = tid & 63;       // i-quad within the batch's 256 dims
    const int bg   = tid >> 6;       // 0..3 -> batch within block
    const int i0   = quad << 2;
    const int b    = blockIdx.x * BT + bg;

    // ---- B-spline basis for 1 batch x 4 dims (registers) ----
    float4 x4 = *reinterpret_cast<const float4*>(x + (size_t)b * IN_DIM + i0);
    float xs[4] = {x4.x, x4.y, x4.z, x4.w};

    float bsp[NB][4];
    #pragma unroll
    for (int ii = 0; ii < 4; ii++) {
        const float* gr = grid + (size_t)(i0 + ii) * GRIDN;
        float g[GRIDN];
        #pragma unroll
        for (int j = 0; j < GRIDN; j++) g[j] = gr[j];
        float xv = xs[ii];
        float B[GRIDN - 1];
        #pragma unroll
        for (int j = 0; j < GRIDN - 1; j++)
            B[j] = (xv >= g[j] && xv < g[j + 1]) ? 1.f : 0.f;
        #pragma unroll
        for (int ki = 1; ki <= 3; ki++) {
            #pragma unroll
            for (int j = 0; j < GRIDN - 1; j++) {
                if (j < GRIDN - 1 - ki) {
                    float left  = (xv - g[j]) / (g[j + ki] - g[j]);
                    float right = (g[j + ki + 1] - xv) / (g[j + ki + 1] - g[j + 1]);
                    B[j] = left * B[j] + right * B[j + 1];
                }
            }
        }
        #pragma unroll
        for (int k = 0; k < NB; k++) bsp[k][ii] = B[k];
    }

    float base[4];
    #pragma unroll
    for (int ii = 0; ii < 4; ii++)
        base[ii] = xs[ii] / (1.f + __expf(-xs[ii]));

    float* ysum     = out;
    float* preacts  = out + (size_t)BATCH * OUT_DIM;
    float* postacts = preacts  + (size_t)BATCH * OUT_DIM * IN_DIM;
    float* postspl  = postacts + (size_t)BATCH * OUT_DIM * IN_DIM;

    const size_t rowbase = (size_t)b * OUT_DIM * IN_DIM + i0;
    const int mysw = quad & 7;

    const unsigned int s_coef_b = (unsigned int)__cvta_generic_to_shared(s_coef);
    const unsigned int s_sb_b   = (unsigned int)__cvta_generic_to_shared(s_sb);
    const unsigned int s_ss_b   = (unsigned int)__cvta_generic_to_shared(s_ss);

    for (int T = 0; T < NT; T++) {
        __syncthreads();   // previous tile's reads complete

        // coef fill: coalesced 16B cp.async, swizzled dst (coef is L2-resident)
        #pragma unroll
        for (int r = 0; r < 8; r++) {
            int c = tid + THREADS * r;          // 0..2047
            int i = c >> 3;
            int q = c & 7;
            const float* src = coef + (size_t)i * (OUT_DIM * NB) + T * (OT * NB) + q * 4;
            int qs = q ^ ((i >> 2) & 7);
            cp_async16(s_coef_b + (unsigned int)((i * 32 + (qs << 2)) * 4), src);
        }
        {
            int ol = tid >> 6;
            int ic = (tid & 63) << 2;
            int o  = T * OT + ol;
            cp_async16(s_sb_b + (unsigned int)((ol * IN_DIM + ic) * 4),
                       g_sbT + (size_t)o * IN_DIM + ic);
            cp_async16(s_ss_b + (unsigned int)((ol * IN_DIM + ic) * 4),
                       g_ssT + (size_t)o * IN_DIM + ic);
        }
        cp_async_wait_all();
        __syncthreads();

        #pragma unroll
        for (int ol = 0; ol < OT; ol++) {
            const int o = T * OT + ol;

            float y[4];
            #pragma unroll
            for (int ii = 0; ii < 4; ii++) y[ii] = 0.f;

            #pragma unroll
            for (int ii = 0; ii < 4; ii++) {
                const int i = i0 + ii;
                float4 ca = *reinterpret_cast<const float4*>(
                    s_coef + i * 32 + (((2 * ol)     ^ mysw) << 2));
                float4 cb = *reinterpret_cast<const float4*>(
                    s_coef + i * 32 + (((2 * ol + 1) ^ mysw) << 2));
                float acc;
                acc  = ca.x * bsp[0][ii];
                acc += ca.y * bsp[1][ii];
                acc += ca.z * bsp[2][ii];
                acc += ca.w * bsp[3][ii];
                acc += cb.x * bsp[4][ii];
                acc += cb.y * bsp[5][ii];
                acc += cb.z * bsp[6][ii];
                acc += cb.w * bsp[7][ii];
                y[ii] = acc;
            }

            float4 sb4 = *reinterpret_cast<const float4*>(s_sb + ol * IN_DIM + i0);
            float4 ss4 = *reinterpret_cast<const float4*>(s_ss + ol * IN_DIM + i0);

            float4 y4  = make_float4(y[0], y[1], y[2], y[3]);
            float4 yy4;
            yy4.x = sb4.x * base[0] + ss4.x * y4.x;
            yy4.y = sb4.y * base[1] + ss4.y * y4.y;
            yy4.z = sb4.z * base[2] + ss4.z * y4.z;
            yy4.w = sb4.w * base[3] + ss4.w * y4.w;

            size_t off = rowbase + (size_t)o * IN_DIM;
            __stcs(reinterpret_cast<float4*>(postspl  + off), y4);
            __stcs(reinterpret_cast<float4*>(postacts + off), yy4);
            __stcs(reinterpret_cast<float4*>(preacts  + off), x4);

            // y_sum: warp covers 128 contiguous i for (b, o)
            float s = (yy4.x + yy4.y) + (yy4.z + yy4.w);
            #pragma unroll
            for (int d = 16; d > 0; d >>= 1)
                s += __shfl_xor_sync(0xffffffffu, s, d);
            if ((tid & 31) == 0)
                atomicAdd(ysum + (size_t)b * OUT_DIM + o, s);
        }
    }
}

extern "C" void kernel_launch(void* const* d_in, const int* in_sizes, int n_in,
                              void* d_out, int out_size) {
    const float* x     = (const float*)d_in[0];
    const float* grid  = (const float*)d_in[1];
    const float* coef  = (const float*)d_in[2];
    const float* sb    = (const float*)d_in[3];
    const float* ssp   = (const float*)d_in[4];
    const float* mask  = (const float*)d_in[5];
    float* out = (float*)d_out;

    (void)in_sizes; (void)n_in; (void)out_size;

    int n = BATCH * OUT_DIM;
    init_kernel<<<(n + 255) / 256, 256>>>(sb, ssp, mask, out);
    kan_kernel<<<BATCH / BT, THREADS>>>(x, grid, coef, out);
}

// round 11
// speedup vs baseline: 1.8524x; 1.8524x over previous
#include <cuda_runtime.h>
#include <cstdint>
#include <math.h>

#define IN_DIM   256
#define OUT_DIM  256
#define GRIDN    12      // NUM + 1 + 2K
#define NB       8       // NUM + K
#define BATCH    2048
#define BT       8       // batches per block
#define THREADS  256
#define OT       4       // outputs per shared tile
#define NT       (OUT_DIM / OT)

// Dynamic smem: [2][256*32] coef + [2][1024] sb + [2][1024] ss = 20480 floats
#define COEF_F   (IN_DIM * OT * NB)      // 8192
#define SCL_F    (OT * IN_DIM)           // 1024
#define SMEM_FLOATS (2 * COEF_F + 4 * SCL_F)
#define SMEM_BYTES  (SMEM_FLOATS * 4)    // 81920

// Fused mask*scale, transposed to [o][i]
__device__ float g_sbT[OUT_DIM * IN_DIM];
__device__ float g_ssT[OUT_DIM * IN_DIM];

__global__ void init_kernel(const float* __restrict__ sb,
                            const float* __restrict__ ssp,
                            const float* __restrict__ mask,
                            float* __restrict__ ysum) {
    int idx = blockIdx.x * blockDim.x + threadIdx.x;
    if (idx < BATCH * OUT_DIM) ysum[idx] = 0.f;
    if (idx < IN_DIM * OUT_DIM) {
        int i = idx >> 8;
        int o = idx & 255;
        float m = mask[idx];
        g_sbT[o * IN_DIM + i] = m * sb[idx];
        g_ssT[o * IN_DIM + i] = m * ssp[idx];
    }
}

__device__ __forceinline__ void cp_async16(unsigned int saddr, const void* gaddr) {
    asm volatile("cp.async.cg.shared.global [%0], [%1], 16;\n"
                 :: "r"(saddr), "l"(gaddr));
}
__device__ __forceinline__ void cp_commit() {
    asm volatile("cp.async.commit_group;\n" ::: "memory");
}
__device__ __forceinline__ void cp_wait1() {
    asm volatile("cp.async.wait_group 1;\n" ::: "memory");
}
__device__ __forceinline__ void cp_wait0() {
    asm volatile("cp.async.wait_group 0;\n" ::: "memory");
}

__global__ __launch_bounds__(THREADS, 2)
void kan_kernel(const float* __restrict__ x,
                const float* __restrict__ grid,
                const float* __restrict__ coef,
                float* __restrict__ out) {
    extern __shared__ float smem[];
    float* s_coef = smem;                       // [2][COEF_F]
    float* s_sb   = smem + 2 * COEF_F;          // [2][SCL_F]
    float* s_ss   = s_sb + 2 * SCL_F;           // [2][SCL_F]

    const int tid  = threadIdx.x;
    const int quad = tid & 63;
    const int bg   = tid >> 6;
    const int i0   = quad << 2;
    const int b0   = blockIdx.x * BT + bg * 2;

    // ---- B-spline basis for 2 batches x 4 dims (registers) ----
    float4 x4[2];
    x4[0] = *reinterpret_cast<const float4*>(x + (size_t)b0 * IN_DIM + i0);
    x4[1] = *reinterpret_cast<const float4*>(x + (size_t)(b0 + 1) * IN_DIM + i0);
    float xs[2][4] = {{x4[0].x, x4[0].y, x4[0].z, x4[0].w},
                      {x4[1].x, x4[1].y, x4[1].z, x4[1].w}};

    float bsp[2][NB][4];
    #pragma unroll
    for (int ii = 0; ii < 4; ii++) {
        const float* gr = grid + (size_t)(i0 + ii) * GRIDN;
        float g[GRIDN];
        #pragma unroll
        for (int j = 0; j < GRIDN; j++) g[j] = gr[j];
        #pragma unroll
        for (int bb = 0; bb < 2; bb++) {
            float xv = xs[bb][ii];
            float B[GRIDN - 1];
            #pragma unroll
            for (int j = 0; j < GRIDN - 1; j++)
                B[j] = (xv >= g[j] && xv < g[j + 1]) ? 1.f : 0.f;
            #pragma unroll
            for (int ki = 1; ki <= 3; ki++) {
                #pragma unroll
                for (int j = 0; j < GRIDN - 1; j++) {
                    if (j < GRIDN - 1 - ki) {
                        float left  = (xv - g[j]) / (g[j + ki] - g[j]);
                        float right = (g[j + ki + 1] - xv) / (g[j + ki + 1] - g[j + 1]);
                        B[j] = left * B[j] + right * B[j + 1];
                    }
                }
            }
            #pragma unroll
            for (int k = 0; k < NB; k++) bsp[bb][k][ii] = B[k];
        }
    }

    float base[2][4];
    #pragma unroll
    for (int bb = 0; bb < 2; bb++)
        #pragma unroll
        for (int ii = 0; ii < 4; ii++) {
            float xv = xs[bb][ii];
            base[bb][ii] = xv / (1.f + __expf(-xv));
        }

    float* ysum     = out;
    float* preacts  = out + (size_t)BATCH * OUT_DIM;
    float* postacts = preacts  + (size_t)BATCH * OUT_DIM * IN_DIM;
    float* postspl  = postacts + (size_t)BATCH * OUT_DIM * IN_DIM;

    const size_t rowbase0 = (size_t)b0 * OUT_DIM * IN_DIM + i0;
    const int mysw = quad & 7;

    const unsigned int s_coef_b = (unsigned int)__cvta_generic_to_shared(s_coef);
    const unsigned int s_sb_b   = (unsigned int)__cvta_generic_to_shared(s_sb);
    const unsigned int s_ss_b   = (unsigned int)__cvta_generic_to_shared(s_ss);

    // Fill one buffer for tile T (coalesced 16B cp.async, swizzled coef dst)
    auto fill = [&](int T, int bufI) {
        unsigned int cbase = s_coef_b + (unsigned int)(bufI * COEF_F * 4);
        #pragma unroll
        for (int r = 0; r < 8; r++) {
            int c = tid + THREADS * r;          // 0..2047
            int i = c >> 3;
            int q = c & 7;
            const float* src = coef + (size_t)i * (OUT_DIM * NB) + T * (OT * NB) + q * 4;
            int qs = q ^ ((i >> 2) & 7);
            cp_async16(cbase + (unsigned int)((i * 32 + (qs << 2)) * 4), src);
        }
        int ol = tid >> 6;
        int ic = (tid & 63) << 2;
        int o  = T * OT + ol;
        cp_async16(s_sb_b + (unsigned int)((bufI * SCL_F + ol * IN_DIM + ic) * 4),
                   g_sbT + (size_t)o * IN_DIM + ic);
        cp_async16(s_ss_b + (unsigned int)((bufI * SCL_F + ol * IN_DIM + ic) * 4),
                   g_ssT + (size_t)o * IN_DIM + ic);
    };

    fill(0, 0);
    cp_commit();

    for (int T = 0; T < NT; T++) {
        const int buf = T & 1;
        __syncthreads();   // all reads of buf^1 (tile T-1) complete before refill

        if (T + 1 < NT) {
            fill(T + 1, buf ^ 1);
            cp_commit();
            cp_wait1();    // tile T's group (issued last iter) has landed
        } else {
            cp_wait0();
        }
        __syncthreads();   // tile T's data visible to all threads

        const float* cbuf = s_coef + buf * COEF_F;
        const float* sbb  = s_sb + buf * SCL_F;
        const float* ssb  = s_ss + buf * SCL_F;

        #pragma unroll
        for (int ol = 0; ol < OT; ol++) {
            const int o = T * OT + ol;

            float y[2][4];
            #pragma unroll
            for (int bb = 0; bb < 2; bb++)
                #pragma unroll
                for (int ii = 0; ii < 4; ii++) y[bb][ii] = 0.f;

            #pragma unroll
            for (int ii = 0; ii < 4; ii++) {
                const int i = i0 + ii;
                float4 ca = *reinterpret_cast<const float4*>(
                    cbuf + i * 32 + (((2 * ol)     ^ mysw) << 2));
                float4 cb = *reinterpret_cast<const float4*>(
                    cbuf + i * 32 + (((2 * ol + 1) ^ mysw) << 2));
                #pragma unroll
                for (int bb = 0; bb < 2; bb++) {
                    float acc;
                    acc  = ca.x * bsp[bb][0][ii];
                    acc += ca.y * bsp[bb][1][ii];
                    acc += ca.z * bsp[bb][2][ii];
                    acc += ca.w * bsp[bb][3][ii];
                    acc += cb.x * bsp[bb][4][ii];
                    acc += cb.y * bsp[bb][5][ii];
                    acc += cb.z * bsp[bb][6][ii];
                    acc += cb.w * bsp[bb][7][ii];
                    y[bb][ii] = acc;
                }
            }

            float4 sb4 = *reinterpret_cast<const float4*>(sbb + ol * IN_DIM + i0);
            float4 ss4 = *reinterpret_cast<const float4*>(ssb + ol * IN_DIM + i0);

            #pragma unroll
            for (int bb = 0; bb < 2; bb++) {
                float4 y4  = make_float4(y[bb][0], y[bb][1], y[bb][2], y[bb][3]);
                float4 yy4;
                yy4.x = sb4.x * base[bb][0] + ss4.x * y4.x;
                yy4.y = sb4.y * base[bb][1] + ss4.y * y4.y;
                yy4.z = sb4.z * base[bb][2] + ss4.z * y4.z;
                yy4.w = sb4.w * base[bb][3] + ss4.w * y4.w;

                size_t off = rowbase0 + (size_t)bb * (OUT_DIM * IN_DIM)
                                      + (size_t)o * IN_DIM;
                __stcs(reinterpret_cast<float4*>(postspl  + off), y4);
                __stcs(reinterpret_cast<float4*>(postacts + off), yy4);
                __stcs(reinterpret_cast<float4*>(preacts  + off), x4[bb]);

                // y_sum: 3-level butterfly (8-lane groups) + 4-lane RED
                float s = (yy4.x + yy4.y) + (yy4.z + yy4.w);
                s += __shfl_xor_sync(0xffffffffu, s, 4);
                s += __shfl_xor_sync(0xffffffffu, s, 2);
                s += __shfl_xor_sync(0xffffffffu, s, 1);
                if ((tid & 7) == 0)
                    atomicAdd(ysum + (size_t)(b0 + bb) * OUT_DIM + o, s);
            }
        }
    }
}

extern "C" void kernel_launch(void* const* d_in, const int* in_sizes, int n_in,
                              void* d_out, int out_size) {
    const float* x     = (const float*)d_in[0];
    const float* grid  = (const float*)d_in[1];
    const float* coef  = (const float*)d_in[2];
    const float* sb    = (const float*)d_in[3];
    const float* ssp   = (const float*)d_in[4];
    const float* mask  = (const float*)d_in[5];
    float* out = (float*)d_out;

    (void)in_sizes; (void)n_in; (void)out_size;

    static int attr_done = 0;
    if (!attr_done) {
        cudaFuncSetAttribute(kan_kernel,
                             cudaFuncAttributeMaxDynamicSharedMemorySize,
                             SMEM_BYTES);
        attr_done = 1;
    }

    int n = BATCH * OUT_DIM;
    init_kernel<<<(n + 255) / 256, 256>>>(sb, ssp, mask, out);
    kan_kernel<<<BATCH / BT, THREADS, SMEM_BYTES>>>(x, grid, coef, out);
}